// round 6
// baseline (speedup 1.0000x reference)
#include <cuda_runtime.h>
#include <math.h>
#include <stdint.h>

#define BN 65536      // batch
#define DD 128        // dim
#define NS 16         // slots
#define NA 4096       // agents
#define EPSN 1e-12f
#define SCALEF 0.08838834764831845f   // 1/sqrt(128)
#define FULLM 0xffffffffu

// ---------------- scratch (static device memory; no runtime allocation) ----
__device__ float g_pqr[BN*DD];    // queries @ Wq^T + bq
__device__ float g_pqw[BN*DD];    // write_queries @ Wq^T + bq
__device__ float g_el[BN*DD];     // write_queries @ We^T + be   (pre-sigmoid)
__device__ float g_al[BN*DD];     // write_queries @ Wa^T + ba   (pre-tanh)
__device__ float g_read[BN*DD];   // attention read vectors
__device__ float g_inten[BN];     // sigmoid(wq @ Wg^T + bg)
__device__ float g_ww[BN*NS];     // write softmax weights
__device__ float g_rmn[NA*NS];    // SCALEF / max(||mem[a,s]||, eps)
__device__ int   g_counts[NA];
__device__ int   g_offsets[NA];
__device__ int   g_cursor[NA];
__device__ int   g_bucket[BN];

// ---------------- per-(agent,slot) reciprocal norms + zero counts ----------
__global__ void k_mnorm(const float* __restrict__ mem) {
    int gt = blockIdx.x * blockDim.x + threadIdx.x;
    if (gt < NA) { g_counts[gt] = 0; g_cursor[gt] = 0; }
    int w = gt >> 5;   // 0..65535 slot rows
    int lane = threadIdx.x & 31;
    float4 v = *(const float4*)(mem + (size_t)w * 128 + lane * 4);
    float s = v.x*v.x + v.y*v.y + v.z*v.z + v.w*v.w;
    #pragma unroll
    for (int o = 16; o > 0; o >>= 1) s += __shfl_xor_sync(FULLM, s, o);
    if (lane == 0) g_rmn[w] = SCALEF / fmaxf(sqrtf(s), EPSN);
}

// ======================= tf32 tensor-core GEMM machinery ====================
#define LDK 68          // 64 k-floats + 4 pad (272B rows, 16B aligned)

__device__ __forceinline__ uint32_t f2tf32(float f) {
    uint32_t u;
    asm("cvt.rna.tf32.f32 %0, %1;" : "=r"(u) : "f"(f));
    return u;
}
__device__ __forceinline__ void ldsm4(uint32_t* r, uint32_t addr) {
    asm volatile("ldmatrix.sync.aligned.m8n8.x4.shared.b16 {%0,%1,%2,%3}, [%4];"
                 : "=r"(r[0]), "=r"(r[1]), "=r"(r[2]), "=r"(r[3]) : "r"(addr));
}
__device__ __forceinline__ void mma1688(float* c, const uint32_t* a, const uint32_t* b) {
    asm volatile("mma.sync.aligned.m16n8k8.row.col.f32.tf32.tf32.f32 "
                 "{%0,%1,%2,%3}, {%4,%5,%6,%7}, {%8,%9}, {%0,%1,%2,%3};"
                 : "+f"(c[0]), "+f"(c[1]), "+f"(c[2]), "+f"(c[3])
                 : "r"(a[0]), "r"(a[1]), "r"(a[2]), "r"(a[3]), "r"(b[0]), "r"(b[1]));
}

// ---------------- 3-way wqueries GEMM: stage X once, loop over Wq/We/Wa -----
__global__ void __launch_bounds__(256, 2)
k_gemm3(const float* __restrict__ wqueries,
        const float* __restrict__ Wq, const float* __restrict__ bq,
        const float* __restrict__ We, const float* __restrict__ be,
        const float* __restrict__ Wa, const float* __restrict__ ba)
{
    extern __shared__ float sh[];
    float* Xs = sh;                     // [2][128][LDK] full K staged once
    float* Ws = sh + 2 * 128 * LDK;     // [128][LDK] per-weight chunk

    const int t = threadIdx.x;
    const int lane = t & 31, wid = t >> 5;
    const int wm = wid & 3;
    const int wn = wid >> 2;
    const int row0 = blockIdx.x * 128;

    // stage X (both 64-k chunks, tf32)
    #pragma unroll
    for (int kc = 0; kc < 2; kc++)
        #pragma unroll
        for (int i = t; i < 2048; i += 256) {
            int m = i >> 4, k4 = (i & 15) << 2;
            float4 v = *(const float4*)(wqueries + (size_t)(row0 + m) * 128 + kc * 64 + k4);
            uint4 u;
            u.x = f2tf32(v.x); u.y = f2tf32(v.y); u.z = f2tf32(v.z); u.w = f2tf32(v.w);
            *(uint4*)(Xs + kc * 128 * LDK + m * LDK + k4) = u;
        }

    const uint32_t xsBase = (uint32_t)__cvta_generic_to_shared(Xs);
    const uint32_t wsBase = (uint32_t)__cvta_generic_to_shared(Ws);
    const uint32_t aAddr0 = xsBase +
        (((wm * 32 + (lane & 15)) * LDK + ((lane >> 4) << 2)) << 2);
    const uint32_t bAddr = wsBase +
        (((wn * 64 + ((lane >> 4) << 3) + (lane & 7)) * LDK + (((lane >> 3) & 1) << 2)) << 2);

    const float* Wlist[3] = {Wq, We, Wa};
    const float* blist[3] = {bq, be, ba};
    float* olist[3] = {g_pqw, g_el, g_al};   // device-code symbol refs (valid)

    #pragma unroll
    for (int wsel = 0; wsel < 3; wsel++) {
        const float* W = Wlist[wsel];
        float acc[2][8][4];
        #pragma unroll
        for (int i = 0; i < 2; i++)
            #pragma unroll
            for (int j = 0; j < 8; j++)
                #pragma unroll
                for (int k = 0; k < 4; k++) acc[i][j][k] = 0.f;

        #pragma unroll
        for (int kc = 0; kc < 2; kc++) {
            #pragma unroll
            for (int i = t; i < 2048; i += 256) {
                int n = i >> 4, k4 = (i & 15) << 2;
                float4 v = *(const float4*)(W + (size_t)n * 128 + kc * 64 + k4);
                uint4 u;
                u.x = f2tf32(v.x); u.y = f2tf32(v.y); u.z = f2tf32(v.z); u.w = f2tf32(v.w);
                *(uint4*)(Ws + n * LDK + k4) = u;
            }
            __syncthreads();
            const uint32_t aAddr = aAddr0 + kc * 128 * LDK * 4;
            #pragma unroll
            for (int ks = 0; ks < 64; ks += 8) {
                uint32_t a[2][4];
                ldsm4(a[0], aAddr + (ks << 2));
                ldsm4(a[1], aAddr + ((16 * LDK + ks) << 2));
                uint32_t b[4][4];
                #pragma unroll
                for (int p = 0; p < 4; p++)
                    ldsm4(b[p], bAddr + ((p * 16 * LDK + ks) << 2));
                #pragma unroll
                for (int mi = 0; mi < 2; mi++)
                    #pragma unroll
                    for (int p = 0; p < 4; p++) {
                        mma1688(acc[mi][p * 2 + 0], a[mi], &b[p][0]);
                        mma1688(acc[mi][p * 2 + 1], a[mi], &b[p][2]);
                    }
            }
            __syncthreads();
        }

        const float* bias = blist[wsel];
        float* out = olist[wsel];
        const int cbase = wn * 64 + (lane & 3) * 2;
        const int rbase = row0 + wm * 32 + (lane >> 2);
        #pragma unroll
        for (int nj = 0; nj < 8; nj++) {
            int col = cbase + nj * 8;
            float b0 = bias[col], b1 = bias[col + 1];
            #pragma unroll
            for (int mi = 0; mi < 2; mi++) {
                float* c = acc[mi][nj];
                int r = rbase + mi * 16;
                *(float2*)(out + (size_t)r * 128 + col) = make_float2(c[0] + b0, c[1] + b1);
                *(float2*)(out + (size_t)(r + 8) * 128 + col) = make_float2(c[2] + b0, c[3] + b1);
            }
        }
    }
}

// ---------------- single GEMM: g_pqr = queries @ Wq^T + bq ------------------
// NOTE: writes g_pqr via device-code symbol (passing __device__ symbols as
// host-side kernel args silently passes the host shadow -> round-5 bug).
__global__ void __launch_bounds__(256, 2)
k_gemm1(const float* __restrict__ X, const float* __restrict__ W,
        const float* __restrict__ bias)
{
    extern __shared__ float sh[];
    float* Xs = sh;
    float* Ws = sh + 128 * LDK;
    float* out = g_pqr;

    const int t = threadIdx.x;
    const int lane = t & 31, wid = t >> 5;
    const int wm = wid & 3;
    const int wn = wid >> 2;
    const int row0 = blockIdx.x * 128;

    float acc[2][8][4];
    #pragma unroll
    for (int i = 0; i < 2; i++)
        #pragma unroll
        for (int j = 0; j < 8; j++)
            #pragma unroll
            for (int k = 0; k < 4; k++) acc[i][j][k] = 0.f;

    const uint32_t xsBase = (uint32_t)__cvta_generic_to_shared(Xs);
    const uint32_t wsBase = (uint32_t)__cvta_generic_to_shared(Ws);
    const uint32_t aAddr = xsBase +
        (((wm * 32 + (lane & 15)) * LDK + ((lane >> 4) << 2)) << 2);
    const uint32_t bAddr = wsBase +
        (((wn * 64 + ((lane >> 4) << 3) + (lane & 7)) * LDK + (((lane >> 3) & 1) << 2)) << 2);

    for (int kc = 0; kc < 128; kc += 64) {
        #pragma unroll
        for (int i = t; i < 2048; i += 256) {
            int m = i >> 4, k4 = (i & 15) << 2;
            float4 v = *(const float4*)(X + (size_t)(row0 + m) * 128 + kc + k4);
            uint4 u;
            u.x = f2tf32(v.x); u.y = f2tf32(v.y); u.z = f2tf32(v.z); u.w = f2tf32(v.w);
            *(uint4*)(Xs + m * LDK + k4) = u;
        }
        #pragma unroll
        for (int i = t; i < 2048; i += 256) {
            int n = i >> 4, k4 = (i & 15) << 2;
            float4 v = *(const float4*)(W + (size_t)n * 128 + kc + k4);
            uint4 u;
            u.x = f2tf32(v.x); u.y = f2tf32(v.y); u.z = f2tf32(v.z); u.w = f2tf32(v.w);
            *(uint4*)(Ws + n * LDK + k4) = u;
        }
        __syncthreads();

        #pragma unroll
        for (int ks = 0; ks < 64; ks += 8) {
            uint32_t a[2][4];
            ldsm4(a[0], aAddr + (ks << 2));
            ldsm4(a[1], aAddr + ((16 * LDK + ks) << 2));
            uint32_t b[4][4];
            #pragma unroll
            for (int p = 0; p < 4; p++)
                ldsm4(b[p], bAddr + ((p * 16 * LDK + ks) << 2));
            #pragma unroll
            for (int mi = 0; mi < 2; mi++)
                #pragma unroll
                for (int p = 0; p < 4; p++) {
                    mma1688(acc[mi][p * 2 + 0], a[mi], &b[p][0]);
                    mma1688(acc[mi][p * 2 + 1], a[mi], &b[p][2]);
                }
        }
        __syncthreads();
    }

    const int cbase = wn * 64 + (lane & 3) * 2;
    const int rbase = row0 + wm * 32 + (lane >> 2);
    #pragma unroll
    for (int nj = 0; nj < 8; nj++) {
        int col = cbase + nj * 8;
        float b0 = bias[col], b1 = bias[col + 1];
        #pragma unroll
        for (int mi = 0; mi < 2; mi++) {
            float* c = acc[mi][nj];
            int r = rbase + mi * 16;
            *(float2*)(out + (size_t)r * 128 + col) = make_float2(c[0] + b0, c[1] + b1);
            *(float2*)(out + (size_t)(r + 8) * 128 + col) = make_float2(c[2] + b0, c[3] + b1);
        }
    }
}

// ---------------- fuse GEMM: outf = LN(gelu(g_read @ Wf^T + bf))*g + b ------
__global__ void __launch_bounds__(256, 2)
k_fuse(const float* __restrict__ Wf, const float* __restrict__ bf,
       const float* __restrict__ lng, const float* __restrict__ lnb,
       float* __restrict__ outf)
{
    extern __shared__ float sh[];
    float* Xs = sh;
    float* Ws = sh + 128 * LDK;

    const int t = threadIdx.x;
    const int lane = t & 31, wid = t >> 5;
    const int wm = wid & 3;
    const int wn = wid >> 2;
    const int row0 = blockIdx.x * 128;

    float acc[2][8][4];
    #pragma unroll
    for (int i = 0; i < 2; i++)
        #pragma unroll
        for (int j = 0; j < 8; j++)
            #pragma unroll
            for (int k = 0; k < 4; k++) acc[i][j][k] = 0.f;

    const uint32_t xsBase = (uint32_t)__cvta_generic_to_shared(Xs);
    const uint32_t wsBase = (uint32_t)__cvta_generic_to_shared(Ws);
    const uint32_t aAddr = xsBase +
        (((wm * 32 + (lane & 15)) * LDK + ((lane >> 4) << 2)) << 2);
    const uint32_t bAddr = wsBase +
        (((wn * 64 + ((lane >> 4) << 3) + (lane & 7)) * LDK + (((lane >> 3) & 1) << 2)) << 2);

    for (int kc = 0; kc < 128; kc += 64) {
        #pragma unroll
        for (int i = t; i < 2048; i += 256) {
            int m = i >> 4, k4 = (i & 15) << 2;
            float4 v = *(const float4*)(g_read + (size_t)(row0 + m) * 128 + kc + k4);
            uint4 u;
            u.x = f2tf32(v.x); u.y = f2tf32(v.y); u.z = f2tf32(v.z); u.w = f2tf32(v.w);
            *(uint4*)(Xs + m * LDK + k4) = u;
        }
        #pragma unroll
        for (int i = t; i < 2048; i += 256) {
            int n = i >> 4, k4 = (i & 15) << 2;
            float4 v = *(const float4*)(Wf + (size_t)n * 128 + kc + k4);
            uint4 u;
            u.x = f2tf32(v.x); u.y = f2tf32(v.y); u.z = f2tf32(v.z); u.w = f2tf32(v.w);
            *(uint4*)(Ws + n * LDK + k4) = u;
        }
        __syncthreads();

        #pragma unroll
        for (int ks = 0; ks < 64; ks += 8) {
            uint32_t a[2][4];
            ldsm4(a[0], aAddr + (ks << 2));
            ldsm4(a[1], aAddr + ((16 * LDK + ks) << 2));
            uint32_t b[4][4];
            #pragma unroll
            for (int p = 0; p < 4; p++)
                ldsm4(b[p], bAddr + ((p * 16 * LDK + ks) << 2));
            #pragma unroll
            for (int mi = 0; mi < 2; mi++)
                #pragma unroll
                for (int p = 0; p < 4; p++) {
                    mma1688(acc[mi][p * 2 + 0], a[mi], &b[p][0]);
                    mma1688(acc[mi][p * 2 + 1], a[mi], &b[p][2]);
                }
        }
        __syncthreads();
    }

    // ---- epilogue: bias + exact gelu, per-row LN via cross-warp partials ----
    const float iSQ2 = 0.7071067811865476f;
    const int cbase = wn * 64 + (lane & 3) * 2;
    float sum[4] = {0.f, 0.f, 0.f, 0.f};
    float sq[4]  = {0.f, 0.f, 0.f, 0.f};

    #pragma unroll
    for (int nj = 0; nj < 8; nj++) {
        int col = cbase + nj * 8;
        float b0 = bf[col], b1 = bf[col + 1];
        #pragma unroll
        for (int mi = 0; mi < 2; mi++) {
            float* c = acc[mi][nj];
            #pragma unroll
            for (int q = 0; q < 4; q++) {
                float v = c[q] + ((q & 1) ? b1 : b0);
                v = 0.5f * v * (1.f + erff(v * iSQ2));
                c[q] = v;
                int ridx = mi * 2 + (q >> 1);
                sum[ridx] += v;
                sq[ridx] = fmaf(v, v, sq[ridx]);
            }
        }
    }
    #pragma unroll
    for (int o = 1; o <= 2; o <<= 1)
        #pragma unroll
        for (int ridx = 0; ridx < 4; ridx++) {
            sum[ridx] += __shfl_xor_sync(FULLM, sum[ridx], o);
            sq[ridx]  += __shfl_xor_sync(FULLM, sq[ridx], o);
        }

    float2* sums = (float2*)sh;    // [128 local rows][2 wn] {sum, sq}
    if ((lane & 3) == 0) {
        #pragma unroll
        for (int ridx = 0; ridx < 4; ridx++) {
            int lr = wm * 32 + (lane >> 2) + (ridx >> 1) * 16 + (ridx & 1) * 8;
            sums[lr * 2 + wn] = make_float2(sum[ridx], sq[ridx]);
        }
    }
    __syncthreads();

    #pragma unroll
    for (int mi = 0; mi < 2; mi++) {
        #pragma unroll
        for (int h = 0; h < 2; h++) {
            int lr = wm * 32 + (lane >> 2) + mi * 16 + h * 8;
            float2 p0 = sums[lr * 2 + 0];
            float2 p1 = sums[lr * 2 + 1];
            float mu = (p0.x + p1.x) * (1.f / 128.f);
            float var = (p0.y + p1.y) * (1.f / 128.f) - mu * mu;
            float rstd = rsqrtf(var + 1e-5f);
            int r = row0 + lr;
            #pragma unroll
            for (int nj = 0; nj < 8; nj++) {
                int col = cbase + nj * 8;
                float v0 = (acc[mi][nj][h * 2 + 0] - mu) * rstd * lng[col] + lnb[col];
                float v1 = (acc[mi][nj][h * 2 + 1] - mu) * rstd * lng[col + 1] + lnb[col + 1];
                *(float2*)(outf + (size_t)r * 128 + col) = make_float2(v0, v1);
            }
        }
    }
}

// ---------------- exclusive scan of counts (4096), 1 block -----------------
__global__ void k_scan() {
    __shared__ int wsum[32];
    const int t = threadIdx.x;
    int v[4];
    #pragma unroll
    for (int i = 0; i < 4; i++) v[i] = g_counts[t * 4 + i];
    int sum = v[0] + v[1] + v[2] + v[3];
    const int lane = t & 31, w = t >> 5;
    int sc = sum;
    #pragma unroll
    for (int o = 1; o < 32; o <<= 1) {
        int n = __shfl_up_sync(FULLM, sc, o);
        if (lane >= o) sc += n;
    }
    if (lane == 31) wsum[w] = sc;
    __syncthreads();
    if (w == 0) {
        int ws = wsum[lane];
        #pragma unroll
        for (int o = 1; o < 32; o <<= 1) {
            int n = __shfl_up_sync(FULLM, ws, o);
            if (lane >= o) ws += n;
        }
        wsum[lane] = ws;
    }
    __syncthreads();
    int base = (w > 0 ? wsum[w - 1] : 0) + sc - sum;
    #pragma unroll
    for (int i = 0; i < 4; i++) { g_offsets[t * 4 + i] = base; base += v[i]; }
}

// ---------------- bucket scatter --------------------------------------------
__global__ void k_scatter(const int* __restrict__ idx) {
    int r = blockIdx.x * blockDim.x + threadIdx.x;
    if (r < BN) {
        int a = idx[r];
        int p = atomicAdd(&g_cursor[a], 1);
        g_bucket[g_offsets[a] + p] = r;
    }
}

// ---------------- paired warp reduction (for query norms) -------------------
__device__ __forceinline__ float pairred(float a0, float a1, int lane) {
    float x = (lane < 16) ? a1 : a0;
    x = __shfl_xor_sync(FULLM, x, 16);
    float t = ((lane < 16) ? a0 : a1) + x;
    t += __shfl_xor_sync(FULLM, t, 8);
    t += __shfl_xor_sync(FULLM, t, 4);
    t += __shfl_xor_sync(FULLM, t, 2);
    t += __shfl_xor_sync(FULLM, t, 1);
    return t;
}

// ---------------- fused attention (read+write) + intensity + histogram -----
__global__ void __launch_bounds__(256)
k_attn(const float* __restrict__ mem, const int* __restrict__ idx,
       const float* __restrict__ wq, const float* __restrict__ Wg,
       const float* __restrict__ bg)
{
    const int t = threadIdx.x, lane = t & 31;
    const int r = blockIdx.x * 8 + (t >> 5);
    const int a = idx[r];

    float4 qr = *(const float4*)(g_pqr + (size_t)r * 128 + lane * 4);
    float4 qw = *(const float4*)(g_pqw + (size_t)r * 128 + lane * 4);
    float nr0 = qr.x*qr.x + qr.y*qr.y + qr.z*qr.z + qr.w*qr.w;
    float nw0 = qw.x*qw.x + qw.y*qw.y + qw.z*qw.z + qw.w*qw.w;
    float nn = pairred(nr0, nw0, lane);        // lanes<16: |qr|^2, >=16: |qw|^2
    float inv = 1.f / fmaxf(sqrtf(nn), EPSN);

    // intensity: sigmoid(wq . Wg + bg) + agent histogram (folded-in k_inten)
    {
        float4 x = *(const float4*)(wq + (size_t)r * 128 + lane * 4);
        float4 g = *(const float4*)(Wg + lane * 4);
        float p = x.x * g.x + x.y * g.y + x.z * g.z + x.w * g.w;
        #pragma unroll
        for (int o = 16; o > 0; o >>= 1) p += __shfl_xor_sync(FULLM, p, o);
        if (lane == 0) {
            g_inten[r] = 1.f / (1.f + __expf(-(p + bg[0])));
            atomicAdd(&g_counts[a], 1);
        }
    }

    float rmn = g_rmn[a * 16 + (lane & 15)];   // reciprocal slot norms (pre-scaled)

    float ax = 0.f, ay = 0.f, az = 0.f, aw2 = 0.f, lr = 0.f, lw = 0.f, myw = 0.f;
    const float* mrow = mem + (size_t)a * 2048;
    #pragma unroll
    for (int j = 0; j < 8; j++) {
        const int s0 = 2 * j, s1 = 2 * j + 1;
        float4 m0 = *(const float4*)(mrow + s0 * 128 + lane * 4);
        float4 m1 = *(const float4*)(mrow + s1 * 128 + lane * 4);
        float p0 = m0.x*qr.x + m0.y*qr.y + m0.z*qr.z + m0.w*qr.w;   // m0.qr
        float p1 = m0.x*qw.x + m0.y*qw.y + m0.z*qw.z + m0.w*qw.w;   // m0.qw
        float p2 = m1.x*qr.x + m1.y*qr.y + m1.z*qr.z + m1.w*qr.w;   // m1.qr
        float p3 = m1.x*qw.x + m1.y*qw.y + m1.z*qw.z + m1.w*qw.w;   // m1.qw

        float x1 = (lane & 16) ? p0 : p1;
        x1 = __shfl_xor_sync(FULLM, x1, 16);
        float A = ((lane & 16) ? p1 : p0) + x1;    // <16: p0, >=16: p1
        float x2 = (lane & 16) ? p2 : p3;
        x2 = __shfl_xor_sync(FULLM, x2, 16);
        float Bv = ((lane & 16) ? p3 : p2) + x2;   // <16: p2, >=16: p3
        float x3 = (lane & 8) ? A : Bv;
        x3 = __shfl_xor_sync(FULLM, x3, 8);
        float C = ((lane & 8) ? Bv : A) + x3;      // octets: p0|p2|p1|p3
        C += __shfl_xor_sync(FULLM, C, 4);
        C += __shfl_xor_sync(FULLM, C, 2);
        C += __shfl_xor_sync(FULLM, C, 1);

        float rmnj = __shfl_sync(FULLM, rmn, s0 + ((lane >> 3) & 1));
        float e = __expf(C * inv * rmnj);          // one exp per thread
        float er0 = __shfl_sync(FULLM, e, 0);
        float er1 = __shfl_sync(FULLM, e, 8);
        float ew0 = __shfl_sync(FULLM, e, 16);
        float ew1 = __shfl_sync(FULLM, e, 24);
        lr += er0 + er1;
        lw += ew0 + ew1;
        ax  = fmaf(er0, m0.x, fmaf(er1, m1.x, ax));
        ay  = fmaf(er0, m0.y, fmaf(er1, m1.y, ay));
        az  = fmaf(er0, m0.z, fmaf(er1, m1.z, az));
        aw2 = fmaf(er0, m0.w, fmaf(er1, m1.w, aw2));
        if (lane == s0) myw = ew0;
        if (lane == s1) myw = ew1;
    }
    float invl = 1.f / lr;
    *(float4*)(g_read + (size_t)r * 128 + lane * 4) =
        make_float4(ax * invl, ay * invl, az * invl, aw2 * invl);
    if (lane < 16) g_ww[r * 16 + lane] = myw / lw;
}

// ---------------- per-agent gather-reduce + memory update + l2norm ---------
__global__ void k_agent(const float* __restrict__ mem, float* __restrict__ outm)
{
    __shared__ float part[8][8];
    __shared__ float nsh[16];
    const int a = blockIdx.x;
    const int t = threadIdx.x;
    const int d = t & 127;
    const int sg = t >> 7;
    const float* mrow = mem + (size_t)a * 2048;
    float* orow = outm + (size_t)a * 2048;
    const int cnt = g_counts[a];
    if (cnt == 0) {
        #pragma unroll
        for (int k = 0; k < 8; k++)
            orow[(sg * 8 + k) * 128 + d] = mrow[(sg * 8 + k) * 128 + d];
        return;
    }
    const int base = g_offsets[a];
    float E[8], A[8];
    #pragma unroll
    for (int k = 0; k < 8; k++) { E[k] = 0.f; A[k] = 0.f; }

    for (int i = 0; i < cnt; i++) {
        int r = g_bucket[base + i];
        float eld = g_el[(size_t)r * 128 + d];
        float ald = g_al[(size_t)r * 128 + d];
        float itn = g_inten[r];
        float4 w0 = *(const float4*)(g_ww + r * 16 + sg * 8);      // uniform addr
        float4 w1 = *(const float4*)(g_ww + r * 16 + sg * 8 + 4);  // (L1 broadcast)
        float ei = itn / (1.f + __expf(-eld));                    // erase * intensity
        float ai = itn * (1.f - 2.f / (__expf(2.f * ald) + 1.f)); // add * intensity
        E[0] = fmaf(w0.x, ei, E[0]); A[0] = fmaf(w0.x, ai, A[0]);
        E[1] = fmaf(w0.y, ei, E[1]); A[1] = fmaf(w0.y, ai, A[1]);
        E[2] = fmaf(w0.z, ei, E[2]); A[2] = fmaf(w0.z, ai, A[2]);
        E[3] = fmaf(w0.w, ei, E[3]); A[3] = fmaf(w0.w, ai, A[3]);
        E[4] = fmaf(w1.x, ei, E[4]); A[4] = fmaf(w1.x, ai, A[4]);
        E[5] = fmaf(w1.y, ei, E[5]); A[5] = fmaf(w1.y, ai, A[5]);
        E[6] = fmaf(w1.z, ei, E[6]); A[6] = fmaf(w1.z, ai, A[6]);
        E[7] = fmaf(w1.w, ei, E[7]); A[7] = fmaf(w1.w, ai, A[7]);
    }

    float nv[8], p2[8];
    #pragma unroll
    for (int k = 0; k < 8; k++) {
        float m = mrow[(sg * 8 + k) * 128 + d];
        nv[k] = m * (1.f - E[k]) + A[k];
        p2[k] = nv[k] * nv[k];
    }
    #pragma unroll
    for (int o = 16; o > 0; o >>= 1) {
        #pragma unroll
        for (int k = 0; k < 8; k++) p2[k] += __shfl_xor_sync(FULLM, p2[k], o);
    }
    const int wp = t >> 5, lane = t & 31;
    if (lane == 0) {
        #pragma unroll
        for (int k = 0; k < 8; k++) part[wp][k] = p2[k];
    }
    __syncthreads();
    if (t < 16) {
        float n2 = part[(t >> 3) * 4 + 0][t & 7] + part[(t >> 3) * 4 + 1][t & 7]
                 + part[(t >> 3) * 4 + 2][t & 7] + part[(t >> 3) * 4 + 3][t & 7];
        nsh[t] = fmaxf(sqrtf(n2), EPSN);
    }
    __syncthreads();
    #pragma unroll
    for (int k = 0; k < 8; k++)
        orow[(sg * 8 + k) * 128 + d] = nv[k] / nsh[sg * 8 + k];
}

// ---------------- launch -----------------------------------------------------
extern "C" void kernel_launch(void* const* d_in, const int* in_sizes, int n_in,
                              void* d_out, int out_size)
{
    const float* queries  = (const float*)d_in[0];
    const float* wqueries = (const float*)d_in[1];
    const float* memory   = (const float*)d_in[2];
    const float* Wq  = (const float*)d_in[3];
    const float* bq  = (const float*)d_in[4];
    const float* We  = (const float*)d_in[5];
    const float* be  = (const float*)d_in[6];
    const float* Wa  = (const float*)d_in[7];
    const float* ba  = (const float*)d_in[8];
    const float* Wf  = (const float*)d_in[9];
    const float* bf  = (const float*)d_in[10];
    const float* lng = (const float*)d_in[11];
    const float* lnb = (const float*)d_in[12];
    const float* Wg  = (const float*)d_in[13];
    const float* bg  = (const float*)d_in[14];
    const int*   idx = (const int*)d_in[15];

    float* outf = (float*)d_out;                 // fused_read [B,128]
    float* outm = outf + (size_t)BN * DD;        // new_memory [4096,16,128]

    const int gemm_smem  = 2 * 128 * LDK * 4;    // 69632 (k_gemm1 / k_fuse)
    const int gemm3_smem = 3 * 128 * LDK * 4;    // 104448 (k_gemm3)
    cudaFuncSetAttribute(k_gemm3, cudaFuncAttributeMaxDynamicSharedMemorySize, gemm3_smem);
    cudaFuncSetAttribute(k_gemm1, cudaFuncAttributeMaxDynamicSharedMemorySize, gemm_smem);
    cudaFuncSetAttribute(k_fuse,  cudaFuncAttributeMaxDynamicSharedMemorySize, gemm_smem);

    k_mnorm<<<NA * NS / 8, 256>>>(memory);                          // + zero counts
    k_gemm3<<<BN / 128, 256, gemm3_smem>>>(wqueries, Wq, bq, We, be, Wa, ba);
    k_gemm1<<<BN / 128, 256, gemm_smem>>>(queries, Wq, bq);
    k_attn<<<BN / 8, 256>>>(memory, idx, wqueries, Wg, bg);         // launch #4 -> ncu
    k_fuse<<<BN / 128, 256, gemm_smem>>>(Wf, bf, lng, lnb, outf);
    k_scan<<<1, 1024>>>();
    k_scatter<<<BN / 256, 256>>>(idx);
    k_agent<<<NA, 256>>>(memory, outm);
}

// round 7
// speedup vs baseline: 1.0131x; 1.0131x over previous
#include <cuda_runtime.h>
#include <math.h>
#include <stdint.h>

#define BN 65536      // batch
#define DD 128        // dim
#define NS 16         // slots
#define NA 4096       // agents
#define EPSN 1e-12f
#define SCALEF 0.08838834764831845f   // 1/sqrt(128)
#define FULLM 0xffffffffu

// ---------------- scratch (static device memory; no runtime allocation) ----
__device__ float g_pqr[BN*DD];    // queries @ Wq^T + bq
__device__ float g_pqw[BN*DD];    // write_queries @ Wq^T + bq
__device__ float g_el[BN*DD];     // write_queries @ We^T + be   (pre-sigmoid)
__device__ float g_al[BN*DD];     // write_queries @ Wa^T + ba   (pre-tanh)
__device__ float g_read[BN*DD];   // attention read vectors
__device__ float g_inten[BN];     // sigmoid(wq @ Wg^T + bg)
__device__ float g_ww[BN*NS];     // write softmax weights
__device__ float g_rmn[NA*NS];    // SCALEF / max(||mem[a,s]||, eps)
__device__ int   g_counts[NA];
__device__ int   g_offsets[NA];
__device__ int   g_cursor[NA];
__device__ int   g_bucket[BN];

// ---------------- per-(agent,slot) reciprocal norms + zero counts ----------
__global__ void k_mnorm(const float* __restrict__ mem) {
    int gt = blockIdx.x * blockDim.x + threadIdx.x;
    if (gt < NA) { g_counts[gt] = 0; g_cursor[gt] = 0; }
    int w = gt >> 5;   // 0..65535 slot rows
    int lane = threadIdx.x & 31;
    float4 v = *(const float4*)(mem + (size_t)w * 128 + lane * 4);
    float s = v.x*v.x + v.y*v.y + v.z*v.z + v.w*v.w;
    #pragma unroll
    for (int o = 16; o > 0; o >>= 1) s += __shfl_xor_sync(FULLM, s, o);
    if (lane == 0) g_rmn[w] = SCALEF / fmaxf(sqrtf(s), EPSN);
}

// ======================= tf32 tensor-core GEMM machinery ====================
#define LDK 68          // 64 k-floats + 4 pad (272B rows, 16B aligned)

__device__ __forceinline__ uint32_t f2tf32(float f) {
    uint32_t u;
    asm("cvt.rna.tf32.f32 %0, %1;" : "=r"(u) : "f"(f));
    return u;
}
__device__ __forceinline__ void ldsm4(uint32_t* r, uint32_t addr) {
    asm volatile("ldmatrix.sync.aligned.m8n8.x4.shared.b16 {%0,%1,%2,%3}, [%4];"
                 : "=r"(r[0]), "=r"(r[1]), "=r"(r[2]), "=r"(r[3]) : "r"(addr));
}
__device__ __forceinline__ void mma1688(float* c, const uint32_t* a, const uint32_t* b) {
    asm volatile("mma.sync.aligned.m16n8k8.row.col.f32.tf32.tf32.f32 "
                 "{%0,%1,%2,%3}, {%4,%5,%6,%7}, {%8,%9}, {%0,%1,%2,%3};"
                 : "+f"(c[0]), "+f"(c[1]), "+f"(c[2]), "+f"(c[3])
                 : "r"(a[0]), "r"(a[1]), "r"(a[2]), "r"(a[3]), "r"(b[0]), "r"(b[1]));
}

// ---------------- 4-way projection GEMM: C[B,128] = X @ W^T + b -------------
// blockIdx.y selects (X, W, bias, out); 69KB smem -> 2 CTA/SM; wqueries
// re-reads across y hit L2 (32MB < 126MB L2).
__global__ void __launch_bounds__(256, 2)
k_gemm_tc(const float* __restrict__ queries,
          const float* __restrict__ wqueries,
          const float* __restrict__ Wq, const float* __restrict__ bq,
          const float* __restrict__ We, const float* __restrict__ be,
          const float* __restrict__ Wa, const float* __restrict__ ba)
{
    extern __shared__ float sh[];
    float* Xs = sh;               // [128][LDK]
    float* Ws = sh + 128 * LDK;   // [128][LDK]

    const float *X, *W, *bias;
    float* out;
    switch (blockIdx.y) {
        case 0:  X = queries;  W = Wq; bias = bq; out = g_pqr; break;
        case 1:  X = wqueries; W = Wq; bias = bq; out = g_pqw; break;
        case 2:  X = wqueries; W = We; bias = be; out = g_el;  break;
        default: X = wqueries; W = Wa; bias = ba; out = g_al;  break;
    }

    const int t = threadIdx.x;
    const int lane = t & 31, wid = t >> 5;
    const int wm = wid & 3;
    const int wn = wid >> 2;
    const int row0 = blockIdx.x * 128;

    float acc[2][8][4];
    #pragma unroll
    for (int i = 0; i < 2; i++)
        #pragma unroll
        for (int j = 0; j < 8; j++)
            #pragma unroll
            for (int k = 0; k < 4; k++) acc[i][j][k] = 0.f;

    const uint32_t xsBase = (uint32_t)__cvta_generic_to_shared(Xs);
    const uint32_t wsBase = (uint32_t)__cvta_generic_to_shared(Ws);
    const uint32_t aAddr = xsBase +
        (((wm * 32 + (lane & 15)) * LDK + ((lane >> 4) << 2)) << 2);
    const uint32_t bAddr = wsBase +
        (((wn * 64 + ((lane >> 4) << 3) + (lane & 7)) * LDK + (((lane >> 3) & 1) << 2)) << 2);

    for (int kc = 0; kc < 128; kc += 64) {
        #pragma unroll
        for (int i = t; i < 2048; i += 256) {
            int m = i >> 4, k4 = (i & 15) << 2;
            float4 v = *(const float4*)(X + (size_t)(row0 + m) * 128 + kc + k4);
            uint4 u;
            u.x = f2tf32(v.x); u.y = f2tf32(v.y); u.z = f2tf32(v.z); u.w = f2tf32(v.w);
            *(uint4*)(Xs + m * LDK + k4) = u;
        }
        #pragma unroll
        for (int i = t; i < 2048; i += 256) {
            int n = i >> 4, k4 = (i & 15) << 2;
            float4 v = *(const float4*)(W + (size_t)n * 128 + kc + k4);
            uint4 u;
            u.x = f2tf32(v.x); u.y = f2tf32(v.y); u.z = f2tf32(v.z); u.w = f2tf32(v.w);
            *(uint4*)(Ws + n * LDK + k4) = u;
        }
        __syncthreads();

        #pragma unroll
        for (int ks = 0; ks < 64; ks += 8) {
            uint32_t a[2][4];
            ldsm4(a[0], aAddr + (ks << 2));
            ldsm4(a[1], aAddr + ((16 * LDK + ks) << 2));
            uint32_t b[4][4];
            #pragma unroll
            for (int p = 0; p < 4; p++)
                ldsm4(b[p], bAddr + ((p * 16 * LDK + ks) << 2));
            #pragma unroll
            for (int mi = 0; mi < 2; mi++)
                #pragma unroll
                for (int p = 0; p < 4; p++) {
                    mma1688(acc[mi][p * 2 + 0], a[mi], &b[p][0]);
                    mma1688(acc[mi][p * 2 + 1], a[mi], &b[p][2]);
                }
        }
        __syncthreads();
    }

    const int cbase = wn * 64 + (lane & 3) * 2;
    const int rbase = row0 + wm * 32 + (lane >> 2);
    #pragma unroll
    for (int nj = 0; nj < 8; nj++) {
        int col = cbase + nj * 8;
        float b0 = bias[col], b1 = bias[col + 1];
        #pragma unroll
        for (int mi = 0; mi < 2; mi++) {
            float* c = acc[mi][nj];
            int r = rbase + mi * 16;
            *(float2*)(out + (size_t)r * 128 + col) = make_float2(c[0] + b0, c[1] + b1);
            *(float2*)(out + (size_t)(r + 8) * 128 + col) = make_float2(c[2] + b0, c[3] + b1);
        }
    }
}

// ---------------- fuse GEMM: outf = LN(gelu(g_read @ Wf^T + bf))*g + b ------
__global__ void __launch_bounds__(256, 2)
k_fuse(const float* __restrict__ Wf, const float* __restrict__ bf,
       const float* __restrict__ lng, const float* __restrict__ lnb,
       float* __restrict__ outf)
{
    extern __shared__ float sh[];
    float* Xs = sh;
    float* Ws = sh + 128 * LDK;

    const int t = threadIdx.x;
    const int lane = t & 31, wid = t >> 5;
    const int wm = wid & 3;
    const int wn = wid >> 2;
    const int row0 = blockIdx.x * 128;

    float acc[2][8][4];
    #pragma unroll
    for (int i = 0; i < 2; i++)
        #pragma unroll
        for (int j = 0; j < 8; j++)
            #pragma unroll
            for (int k = 0; k < 4; k++) acc[i][j][k] = 0.f;

    const uint32_t xsBase = (uint32_t)__cvta_generic_to_shared(Xs);
    const uint32_t wsBase = (uint32_t)__cvta_generic_to_shared(Ws);
    const uint32_t aAddr = xsBase +
        (((wm * 32 + (lane & 15)) * LDK + ((lane >> 4) << 2)) << 2);
    const uint32_t bAddr = wsBase +
        (((wn * 64 + ((lane >> 4) << 3) + (lane & 7)) * LDK + (((lane >> 3) & 1) << 2)) << 2);

    for (int kc = 0; kc < 128; kc += 64) {
        #pragma unroll
        for (int i = t; i < 2048; i += 256) {
            int m = i >> 4, k4 = (i & 15) << 2;
            float4 v = *(const float4*)(g_read + (size_t)(row0 + m) * 128 + kc + k4);
            uint4 u;
            u.x = f2tf32(v.x); u.y = f2tf32(v.y); u.z = f2tf32(v.z); u.w = f2tf32(v.w);
            *(uint4*)(Xs + m * LDK + k4) = u;
        }
        #pragma unroll
        for (int i = t; i < 2048; i += 256) {
            int n = i >> 4, k4 = (i & 15) << 2;
            float4 v = *(const float4*)(Wf + (size_t)n * 128 + kc + k4);
            uint4 u;
            u.x = f2tf32(v.x); u.y = f2tf32(v.y); u.z = f2tf32(v.z); u.w = f2tf32(v.w);
            *(uint4*)(Ws + n * LDK + k4) = u;
        }
        __syncthreads();

        #pragma unroll
        for (int ks = 0; ks < 64; ks += 8) {
            uint32_t a[2][4];
            ldsm4(a[0], aAddr + (ks << 2));
            ldsm4(a[1], aAddr + ((16 * LDK + ks) << 2));
            uint32_t b[4][4];
            #pragma unroll
            for (int p = 0; p < 4; p++)
                ldsm4(b[p], bAddr + ((p * 16 * LDK + ks) << 2));
            #pragma unroll
            for (int mi = 0; mi < 2; mi++)
                #pragma unroll
                for (int p = 0; p < 4; p++) {
                    mma1688(acc[mi][p * 2 + 0], a[mi], &b[p][0]);
                    mma1688(acc[mi][p * 2 + 1], a[mi], &b[p][2]);
                }
        }
        __syncthreads();
    }

    // ---- epilogue: bias + exact gelu, per-row LN via cross-warp partials ----
    const float iSQ2 = 0.7071067811865476f;
    const int cbase = wn * 64 + (lane & 3) * 2;
    float sum[4] = {0.f, 0.f, 0.f, 0.f};
    float sq[4]  = {0.f, 0.f, 0.f, 0.f};

    #pragma unroll
    for (int nj = 0; nj < 8; nj++) {
        int col = cbase + nj * 8;
        float b0 = bf[col], b1 = bf[col + 1];
        #pragma unroll
        for (int mi = 0; mi < 2; mi++) {
            float* c = acc[mi][nj];
            #pragma unroll
            for (int q = 0; q < 4; q++) {
                float v = c[q] + ((q & 1) ? b1 : b0);
                v = 0.5f * v * (1.f + erff(v * iSQ2));
                c[q] = v;
                int ridx = mi * 2 + (q >> 1);
                sum[ridx] += v;
                sq[ridx] = fmaf(v, v, sq[ridx]);
            }
        }
    }
    #pragma unroll
    for (int o = 1; o <= 2; o <<= 1)
        #pragma unroll
        for (int ridx = 0; ridx < 4; ridx++) {
            sum[ridx] += __shfl_xor_sync(FULLM, sum[ridx], o);
            sq[ridx]  += __shfl_xor_sync(FULLM, sq[ridx], o);
        }

    float2* sums = (float2*)sh;    // [128 local rows][2 wn] {sum, sq}
    if ((lane & 3) == 0) {
        #pragma unroll
        for (int ridx = 0; ridx < 4; ridx++) {
            int lr = wm * 32 + (lane >> 2) + (ridx >> 1) * 16 + (ridx & 1) * 8;
            sums[lr * 2 + wn] = make_float2(sum[ridx], sq[ridx]);
        }
    }
    __syncthreads();

    #pragma unroll
    for (int mi = 0; mi < 2; mi++) {
        #pragma unroll
        for (int h = 0; h < 2; h++) {
            int lr = wm * 32 + (lane >> 2) + mi * 16 + h * 8;
            float2 p0 = sums[lr * 2 + 0];
            float2 p1 = sums[lr * 2 + 1];
            float mu = (p0.x + p1.x) * (1.f / 128.f);
            float var = (p0.y + p1.y) * (1.f / 128.f) - mu * mu;
            float rstd = rsqrtf(var + 1e-5f);
            int r = row0 + lr;
            #pragma unroll
            for (int nj = 0; nj < 8; nj++) {
                int col = cbase + nj * 8;
                float v0 = (acc[mi][nj][h * 2 + 0] - mu) * rstd * lng[col] + lnb[col];
                float v1 = (acc[mi][nj][h * 2 + 1] - mu) * rstd * lng[col + 1] + lnb[col + 1];
                *(float2*)(outf + (size_t)r * 128 + col) = make_float2(v0, v1);
            }
        }
    }
}

// ---------------- exclusive scan of counts (4096), 1 block -----------------
__global__ void k_scan() {
    __shared__ int wsum[32];
    const int t = threadIdx.x;
    int v[4];
    #pragma unroll
    for (int i = 0; i < 4; i++) v[i] = g_counts[t * 4 + i];
    int sum = v[0] + v[1] + v[2] + v[3];
    const int lane = t & 31, w = t >> 5;
    int sc = sum;
    #pragma unroll
    for (int o = 1; o < 32; o <<= 1) {
        int n = __shfl_up_sync(FULLM, sc, o);
        if (lane >= o) sc += n;
    }
    if (lane == 31) wsum[w] = sc;
    __syncthreads();
    if (w == 0) {
        int ws = wsum[lane];
        #pragma unroll
        for (int o = 1; o < 32; o <<= 1) {
            int n = __shfl_up_sync(FULLM, ws, o);
            if (lane >= o) ws += n;
        }
        wsum[lane] = ws;
    }
    __syncthreads();
    int base = (w > 0 ? wsum[w - 1] : 0) + sc - sum;
    #pragma unroll
    for (int i = 0; i < 4; i++) { g_offsets[t * 4 + i] = base; base += v[i]; }
}

// ---------------- bucket scatter --------------------------------------------
__global__ void k_scatter(const int* __restrict__ idx) {
    int r = blockIdx.x * blockDim.x + threadIdx.x;
    if (r < BN) {
        int a = idx[r];
        int p = atomicAdd(&g_cursor[a], 1);
        g_bucket[g_offsets[a] + p] = r;
    }
}

// ---------------- paired warp reduction (for query norms) -------------------
__device__ __forceinline__ float pairred(float a0, float a1, int lane) {
    float x = (lane < 16) ? a1 : a0;
    x = __shfl_xor_sync(FULLM, x, 16);
    float t = ((lane < 16) ? a0 : a1) + x;
    t += __shfl_xor_sync(FULLM, t, 8);
    t += __shfl_xor_sync(FULLM, t, 4);
    t += __shfl_xor_sync(FULLM, t, 2);
    t += __shfl_xor_sync(FULLM, t, 1);
    return t;
}

// ---------------- fused attention (read+write) + intensity + histogram -----
__global__ void __launch_bounds__(256)
k_attn(const float* __restrict__ mem, const int* __restrict__ idx,
       const float* __restrict__ wq, const float* __restrict__ Wg,
       const float* __restrict__ bg)
{
    const int t = threadIdx.x, lane = t & 31;
    const int r = blockIdx.x * 8 + (t >> 5);
    const int a = idx[r];

    float4 qr = *(const float4*)(g_pqr + (size_t)r * 128 + lane * 4);
    float4 qw = *(const float4*)(g_pqw + (size_t)r * 128 + lane * 4);
    float nr0 = qr.x*qr.x + qr.y*qr.y + qr.z*qr.z + qr.w*qr.w;
    float nw0 = qw.x*qw.x + qw.y*qw.y + qw.z*qw.z + qw.w*qw.w;
    float nn = pairred(nr0, nw0, lane);        // lanes<16: |qr|^2, >=16: |qw|^2
    float inv = 1.f / fmaxf(sqrtf(nn), EPSN);

    // intensity: sigmoid(wq . Wg + bg) + agent histogram (folded-in k_inten)
    {
        float4 x = *(const float4*)(wq + (size_t)r * 128 + lane * 4);
        float4 g = *(const float4*)(Wg + lane * 4);
        float p = x.x * g.x + x.y * g.y + x.z * g.z + x.w * g.w;
        #pragma unroll
        for (int o = 16; o > 0; o >>= 1) p += __shfl_xor_sync(FULLM, p, o);
        if (lane == 0) {
            g_inten[r] = 1.f / (1.f + __expf(-(p + bg[0])));
            atomicAdd(&g_counts[a], 1);
        }
    }

    float rmn = g_rmn[a * 16 + (lane & 15)];   // reciprocal slot norms (pre-scaled)

    float ax = 0.f, ay = 0.f, az = 0.f, aw2 = 0.f, lr = 0.f, lw = 0.f, myw = 0.f;
    const float* mrow = mem + (size_t)a * 2048;
    #pragma unroll
    for (int j = 0; j < 8; j++) {
        const int s0 = 2 * j, s1 = 2 * j + 1;
        float4 m0 = *(const float4*)(mrow + s0 * 128 + lane * 4);
        float4 m1 = *(const float4*)(mrow + s1 * 128 + lane * 4);
        float p0 = m0.x*qr.x + m0.y*qr.y + m0.z*qr.z + m0.w*qr.w;   // m0.qr
        float p1 = m0.x*qw.x + m0.y*qw.y + m0.z*qw.z + m0.w*qw.w;   // m0.qw
        float p2 = m1.x*qr.x + m1.y*qr.y + m1.z*qr.z + m1.w*qr.w;   // m1.qr
        float p3 = m1.x*qw.x + m1.y*qw.y + m1.z*qw.z + m1.w*qw.w;   // m1.qw

        float x1 = (lane & 16) ? p0 : p1;
        x1 = __shfl_xor_sync(FULLM, x1, 16);
        float A = ((lane & 16) ? p1 : p0) + x1;    // <16: p0, >=16: p1
        float x2 = (lane & 16) ? p2 : p3;
        x2 = __shfl_xor_sync(FULLM, x2, 16);
        float Bv = ((lane & 16) ? p3 : p2) + x2;   // <16: p2, >=16: p3
        float x3 = (lane & 8) ? A : Bv;
        x3 = __shfl_xor_sync(FULLM, x3, 8);
        float C = ((lane & 8) ? Bv : A) + x3;      // octets: p0|p2|p1|p3
        C += __shfl_xor_sync(FULLM, C, 4);
        C += __shfl_xor_sync(FULLM, C, 2);
        C += __shfl_xor_sync(FULLM, C, 1);

        float rmnj = __shfl_sync(FULLM, rmn, s0 + ((lane >> 3) & 1));
        float e = __expf(C * inv * rmnj);          // one exp per thread
        float er0 = __shfl_sync(FULLM, e, 0);
        float er1 = __shfl_sync(FULLM, e, 8);
        float ew0 = __shfl_sync(FULLM, e, 16);
        float ew1 = __shfl_sync(FULLM, e, 24);
        lr += er0 + er1;
        lw += ew0 + ew1;
        ax  = fmaf(er0, m0.x, fmaf(er1, m1.x, ax));
        ay  = fmaf(er0, m0.y, fmaf(er1, m1.y, ay));
        az  = fmaf(er0, m0.z, fmaf(er1, m1.z, az));
        aw2 = fmaf(er0, m0.w, fmaf(er1, m1.w, aw2));
        if (lane == s0) myw = ew0;
        if (lane == s1) myw = ew1;
    }
    float invl = 1.f / lr;
    *(float4*)(g_read + (size_t)r * 128 + lane * 4) =
        make_float4(ax * invl, ay * invl, az * invl, aw2 * invl);
    if (lane < 16) g_ww[r * 16 + lane] = myw / lw;
}

// ---------------- per-agent gather-reduce + memory update + l2norm ---------
__global__ void k_agent(const float* __restrict__ mem, float* __restrict__ outm)
{
    __shared__ float part[8][8];
    __shared__ float nsh[16];
    const int a = blockIdx.x;
    const int t = threadIdx.x;
    const int d = t & 127;
    const int sg = t >> 7;
    const float* mrow = mem + (size_t)a * 2048;
    float* orow = outm + (size_t)a * 2048;
    const int cnt = g_counts[a];
    if (cnt == 0) {
        #pragma unroll
        for (int k = 0; k < 8; k++)
            orow[(sg * 8 + k) * 128 + d] = mrow[(sg * 8 + k) * 128 + d];
        return;
    }
    const int base = g_offsets[a];
    float E[8], A[8];
    #pragma unroll
    for (int k = 0; k < 8; k++) { E[k] = 0.f; A[k] = 0.f; }

    for (int i = 0; i < cnt; i++) {
        int r = g_bucket[base + i];
        float eld = g_el[(size_t)r * 128 + d];
        float ald = g_al[(size_t)r * 128 + d];
        float itn = g_inten[r];
        float4 w0 = *(const float4*)(g_ww + r * 16 + sg * 8);      // uniform addr
        float4 w1 = *(const float4*)(g_ww + r * 16 + sg * 8 + 4);  // (L1 broadcast)
        float ei = itn / (1.f + __expf(-eld));                    // erase * intensity
        float ai = itn * (1.f - 2.f / (__expf(2.f * ald) + 1.f)); // add * intensity
        E[0] = fmaf(w0.x, ei, E[0]); A[0] = fmaf(w0.x, ai, A[0]);
        E[1] = fmaf(w0.y, ei, E[1]); A[1] = fmaf(w0.y, ai, A[1]);
        E[2] = fmaf(w0.z, ei, E[2]); A[2] = fmaf(w0.z, ai, A[2]);
        E[3] = fmaf(w0.w, ei, E[3]); A[3] = fmaf(w0.w, ai, A[3]);
        E[4] = fmaf(w1.x, ei, E[4]); A[4] = fmaf(w1.x, ai, A[4]);
        E[5] = fmaf(w1.y, ei, E[5]); A[5] = fmaf(w1.y, ai, A[5]);
        E[6] = fmaf(w1.z, ei, E[6]); A[6] = fmaf(w1.z, ai, A[6]);
        E[7] = fmaf(w1.w, ei, E[7]); A[7] = fmaf(w1.w, ai, A[7]);
    }

    float nv[8], p2[8];
    #pragma unroll
    for (int k = 0; k < 8; k++) {
        float m = mrow[(sg * 8 + k) * 128 + d];
        nv[k] = m * (1.f - E[k]) + A[k];
        p2[k] = nv[k] * nv[k];
    }
    #pragma unroll
    for (int o = 16; o > 0; o >>= 1) {
        #pragma unroll
        for (int k = 0; k < 8; k++) p2[k] += __shfl_xor_sync(FULLM, p2[k], o);
    }
    const int wp = t >> 5, lane = t & 31;
    if (lane == 0) {
        #pragma unroll
        for (int k = 0; k < 8; k++) part[wp][k] = p2[k];
    }
    __syncthreads();
    if (t < 16) {
        float n2 = part[(t >> 3) * 4 + 0][t & 7] + part[(t >> 3) * 4 + 1][t & 7]
                 + part[(t >> 3) * 4 + 2][t & 7] + part[(t >> 3) * 4 + 3][t & 7];
        nsh[t] = fmaxf(sqrtf(n2), EPSN);
    }
    __syncthreads();
    #pragma unroll
    for (int k = 0; k < 8; k++)
        orow[(sg * 8 + k) * 128 + d] = nv[k] / nsh[sg * 8 + k];
}

// ---------------- launch -----------------------------------------------------
extern "C" void kernel_launch(void* const* d_in, const int* in_sizes, int n_in,
                              void* d_out, int out_size)
{
    const float* queries  = (const float*)d_in[0];
    const float* wqueries = (const float*)d_in[1];
    const float* memory   = (const float*)d_in[2];
    const float* Wq  = (const float*)d_in[3];
    const float* bq  = (const float*)d_in[4];
    const float* We  = (const float*)d_in[5];
    const float* be  = (const float*)d_in[6];
    const float* Wa  = (const float*)d_in[7];
    const float* ba  = (const float*)d_in[8];
    const float* Wf  = (const float*)d_in[9];
    const float* bf  = (const float*)d_in[10];
    const float* lng = (const float*)d_in[11];
    const float* lnb = (const float*)d_in[12];
    const float* Wg  = (const float*)d_in[13];
    const float* bg  = (const float*)d_in[14];
    const int*   idx = (const int*)d_in[15];

    float* outf = (float*)d_out;                 // fused_read [B,128]
    float* outm = outf + (size_t)BN * DD;        // new_memory [4096,16,128]

    const int gemm_smem = 2 * 128 * LDK * 4;     // 69632
    cudaFuncSetAttribute(k_gemm_tc, cudaFuncAttributeMaxDynamicSharedMemorySize, gemm_smem);
    cudaFuncSetAttribute(k_fuse,    cudaFuncAttributeMaxDynamicSharedMemorySize, gemm_smem);

    k_mnorm<<<NA * NS / 8, 256>>>(memory);                          // + zero counts
    k_gemm_tc<<<dim3(BN / 128, 4), 256, gemm_smem>>>(queries, wqueries, Wq, bq, We, be, Wa, ba);
    k_attn<<<BN / 8, 256>>>(memory, idx, wqueries, Wg, bg);
    k_fuse<<<BN / 128, 256, gemm_smem>>>(Wf, bf, lng, lnb, outf);   // launch #4 -> ncu
    k_scan<<<1, 1024>>>();
    k_scatter<<<BN / 256, 256>>>(idx);
    k_agent<<<NA, 256>>>(memory, outm);
}

// round 9
// speedup vs baseline: 1.0348x; 1.0214x over previous
#include <cuda_runtime.h>
#include <math.h>
#include <stdint.h>

#define BN 65536      // batch
#define DD 128        // dim
#define NS 16         // slots
#define NA 4096       // agents
#define EPSN 1e-12f
#define SCALEF 0.08838834764831845f   // 1/sqrt(128)
#define FULLM 0xffffffffu

// ---------------- scratch (static device memory; no runtime allocation) ----
__device__ float g_pqr[BN*DD];    // queries @ Wq^T + bq
__device__ float g_pqw[BN*DD];    // write_queries @ Wq^T + bq
__device__ float g_el[BN*DD];     // write_queries @ We^T + be   (pre-sigmoid)
__device__ float g_al[BN*DD];     // write_queries @ Wa^T + ba   (pre-tanh)
__device__ float g_read[BN*DD];   // attention read vectors
__device__ float g_inten[BN];     // sigmoid(wq @ Wg^T + bg)
__device__ float g_ww[BN*NS];     // write softmax weights
__device__ float g_rmn[NA*NS];    // SCALEF / max(||mem[a,s]||, eps)
__device__ int   g_counts[NA];
__device__ int   g_offsets[NA];
__device__ int   g_cursor[NA];
__device__ int   g_bucket[BN];

// ---------------- per-(agent,slot) reciprocal norms + zero counts ----------
__global__ void k_mnorm(const float* __restrict__ mem) {
    int gt = blockIdx.x * blockDim.x + threadIdx.x;
    if (gt < NA) { g_counts[gt] = 0; g_cursor[gt] = 0; }
    int w = gt >> 5;   // 0..65535 slot rows
    int lane = threadIdx.x & 31;
    float4 v = *(const float4*)(mem + (size_t)w * 128 + lane * 4);
    float s = v.x*v.x + v.y*v.y + v.z*v.z + v.w*v.w;
    #pragma unroll
    for (int o = 16; o > 0; o >>= 1) s += __shfl_xor_sync(FULLM, s, o);
    if (lane == 0) g_rmn[w] = SCALEF / fmaxf(sqrtf(s), EPSN);
}

// ======================= tf32 tensor-core GEMM machinery ====================
#define LDK 68          // 64 k-floats + 4 pad (272B rows, 16B aligned)

__device__ __forceinline__ uint32_t f2tf32(float f) {
    uint32_t u;
    asm("cvt.rna.tf32.f32 %0, %1;" : "=r"(u) : "f"(f));
    return u;
}
__device__ __forceinline__ void ldsm4(uint32_t* r, uint32_t addr) {
    asm volatile("ldmatrix.sync.aligned.m8n8.x4.shared.b16 {%0,%1,%2,%3}, [%4];"
                 : "=r"(r[0]), "=r"(r[1]), "=r"(r[2]), "=r"(r[3]) : "r"(addr));
}
__device__ __forceinline__ void mma1688(float* c, const uint32_t* a, const uint32_t* b) {
    asm volatile("mma.sync.aligned.m16n8k8.row.col.f32.tf32.tf32.f32 "
                 "{%0,%1,%2,%3}, {%4,%5,%6,%7}, {%8,%9}, {%0,%1,%2,%3};"
                 : "+f"(c[0]), "+f"(c[1]), "+f"(c[2]), "+f"(c[3])
                 : "r"(a[0]), "r"(a[1]), "r"(a[2]), "r"(a[3]), "r"(b[0]), "r"(b[1]));
}

// ---------------- 2x2-way projection GEMM: C[B,128] = X @ W^T + b -----------
// (blockIdx.y + ybase) selects the combo; ybase splits Wq-pair vs We/Wa-pair
// across two launches so the second can overlap k_attn on another stream.
__global__ void __launch_bounds__(256, 2)
k_gemm_tc(const float* __restrict__ queries,
          const float* __restrict__ wqueries,
          const float* __restrict__ Wq, const float* __restrict__ bq,
          const float* __restrict__ We, const float* __restrict__ be,
          const float* __restrict__ Wa, const float* __restrict__ ba,
          int ybase)
{
    extern __shared__ float sh[];
    float* Xs = sh;               // [128][LDK]
    float* Ws = sh + 128 * LDK;   // [128][LDK]

    const float *X, *W, *bias;
    float* out;
    switch (blockIdx.y + ybase) {
        case 0:  X = queries;  W = Wq; bias = bq; out = g_pqr; break;
        case 1:  X = wqueries; W = Wq; bias = bq; out = g_pqw; break;
        case 2:  X = wqueries; W = We; bias = be; out = g_el;  break;
        default: X = wqueries; W = Wa; bias = ba; out = g_al;  break;
    }

    const int t = threadIdx.x;
    const int lane = t & 31, wid = t >> 5;
    const int wm = wid & 3;
    const int wn = wid >> 2;
    const int row0 = blockIdx.x * 128;

    float acc[2][8][4];
    #pragma unroll
    for (int i = 0; i < 2; i++)
        #pragma unroll
        for (int j = 0; j < 8; j++)
            #pragma unroll
            for (int k = 0; k < 4; k++) acc[i][j][k] = 0.f;

    const uint32_t xsBase = (uint32_t)__cvta_generic_to_shared(Xs);
    const uint32_t wsBase = (uint32_t)__cvta_generic_to_shared(Ws);
    const uint32_t aAddr = xsBase +
        (((wm * 32 + (lane & 15)) * LDK + ((lane >> 4) << 2)) << 2);
    const uint32_t bAddr = wsBase +
        (((wn * 64 + ((lane >> 4) << 3) + (lane & 7)) * LDK + (((lane >> 3) & 1) << 2)) << 2);

    for (int kc = 0; kc < 128; kc += 64) {
        #pragma unroll
        for (int i = t; i < 2048; i += 256) {
            int m = i >> 4, k4 = (i & 15) << 2;
            float4 v = *(const float4*)(X + (size_t)(row0 + m) * 128 + kc + k4);
            uint4 u;
            u.x = f2tf32(v.x); u.y = f2tf32(v.y); u.z = f2tf32(v.z); u.w = f2tf32(v.w);
            *(uint4*)(Xs + m * LDK + k4) = u;
        }
        #pragma unroll
        for (int i = t; i < 2048; i += 256) {
            int n = i >> 4, k4 = (i & 15) << 2;
            float4 v = *(const float4*)(W + (size_t)n * 128 + kc + k4);
            uint4 u;
            u.x = f2tf32(v.x); u.y = f2tf32(v.y); u.z = f2tf32(v.z); u.w = f2tf32(v.w);
            *(uint4*)(Ws + n * LDK + k4) = u;
        }
        __syncthreads();

        #pragma unroll
        for (int ks = 0; ks < 64; ks += 8) {
            uint32_t a[2][4];
            ldsm4(a[0], aAddr + (ks << 2));
            ldsm4(a[1], aAddr + ((16 * LDK + ks) << 2));
            uint32_t b[4][4];
            #pragma unroll
            for (int p = 0; p < 4; p++)
                ldsm4(b[p], bAddr + ((p * 16 * LDK + ks) << 2));
            #pragma unroll
            for (int mi = 0; mi < 2; mi++)
                #pragma unroll
                for (int p = 0; p < 4; p++) {
                    mma1688(acc[mi][p * 2 + 0], a[mi], &b[p][0]);
                    mma1688(acc[mi][p * 2 + 1], a[mi], &b[p][2]);
                }
        }
        __syncthreads();
    }

    const int cbase = wn * 64 + (lane & 3) * 2;
    const int rbase = row0 + wm * 32 + (lane >> 2);
    #pragma unroll
    for (int nj = 0; nj < 8; nj++) {
        int col = cbase + nj * 8;
        float b0 = bias[col], b1 = bias[col + 1];
        #pragma unroll
        for (int mi = 0; mi < 2; mi++) {
            float* c = acc[mi][nj];
            int r = rbase + mi * 16;
            *(float2*)(out + (size_t)r * 128 + col) = make_float2(c[0] + b0, c[1] + b1);
            *(float2*)(out + (size_t)(r + 8) * 128 + col) = make_float2(c[2] + b0, c[3] + b1);
        }
    }
}

// ---------------- fuse GEMM: outf = LN(gelu(g_read @ Wf^T + bf))*g + b ------
__global__ void __launch_bounds__(256, 2)
k_fuse(const float* __restrict__ Wf, const float* __restrict__ bf,
       const float* __restrict__ lng, const float* __restrict__ lnb,
       float* __restrict__ outf)
{
    extern __shared__ float sh[];
    float* Xs = sh;
    float* Ws = sh + 128 * LDK;

    const int t = threadIdx.x;
    const int lane = t & 31, wid = t >> 5;
    const int wm = wid & 3;
    const int wn = wid >> 2;
    const int row0 = blockIdx.x * 128;

    float acc[2][8][4];
    #pragma unroll
    for (int i = 0; i < 2; i++)
        #pragma unroll
        for (int j = 0; j < 8; j++)
            #pragma unroll
            for (int k = 0; k < 4; k++) acc[i][j][k] = 0.f;

    const uint32_t xsBase = (uint32_t)__cvta_generic_to_shared(Xs);
    const uint32_t wsBase = (uint32_t)__cvta_generic_to_shared(Ws);
    const uint32_t aAddr = xsBase +
        (((wm * 32 + (lane & 15)) * LDK + ((lane >> 4) << 2)) << 2);
    const uint32_t bAddr = wsBase +
        (((wn * 64 + ((lane >> 4) << 3) + (lane & 7)) * LDK + (((lane >> 3) & 1) << 2)) << 2);

    for (int kc = 0; kc < 128; kc += 64) {
        #pragma unroll
        for (int i = t; i < 2048; i += 256) {
            int m = i >> 4, k4 = (i & 15) << 2;
            float4 v = *(const float4*)(g_read + (size_t)(row0 + m) * 128 + kc + k4);
            uint4 u;
            u.x = f2tf32(v.x); u.y = f2tf32(v.y); u.z = f2tf32(v.z); u.w = f2tf32(v.w);
            *(uint4*)(Xs + m * LDK + k4) = u;
        }
        #pragma unroll
        for (int i = t; i < 2048; i += 256) {
            int n = i >> 4, k4 = (i & 15) << 2;
            float4 v = *(const float4*)(Wf + (size_t)n * 128 + kc + k4);
            uint4 u;
            u.x = f2tf32(v.x); u.y = f2tf32(v.y); u.z = f2tf32(v.z); u.w = f2tf32(v.w);
            *(uint4*)(Ws + n * LDK + k4) = u;
        }
        __syncthreads();

        #pragma unroll
        for (int ks = 0; ks < 64; ks += 8) {
            uint32_t a[2][4];
            ldsm4(a[0], aAddr + (ks << 2));
            ldsm4(a[1], aAddr + ((16 * LDK + ks) << 2));
            uint32_t b[4][4];
            #pragma unroll
            for (int p = 0; p < 4; p++)
                ldsm4(b[p], bAddr + ((p * 16 * LDK + ks) << 2));
            #pragma unroll
            for (int mi = 0; mi < 2; mi++)
                #pragma unroll
                for (int p = 0; p < 4; p++) {
                    mma1688(acc[mi][p * 2 + 0], a[mi], &b[p][0]);
                    mma1688(acc[mi][p * 2 + 1], a[mi], &b[p][2]);
                }
        }
        __syncthreads();
    }

    const float iSQ2 = 0.7071067811865476f;
    const int cbase = wn * 64 + (lane & 3) * 2;
    float sum[4] = {0.f, 0.f, 0.f, 0.f};
    float sq[4]  = {0.f, 0.f, 0.f, 0.f};

    #pragma unroll
    for (int nj = 0; nj < 8; nj++) {
        int col = cbase + nj * 8;
        float b0 = bf[col], b1 = bf[col + 1];
        #pragma unroll
        for (int mi = 0; mi < 2; mi++) {
            float* c = acc[mi][nj];
            #pragma unroll
            for (int q = 0; q < 4; q++) {
                float v = c[q] + ((q & 1) ? b1 : b0);
                v = 0.5f * v * (1.f + erff(v * iSQ2));
                c[q] = v;
                int ridx = mi * 2 + (q >> 1);
                sum[ridx] += v;
                sq[ridx] = fmaf(v, v, sq[ridx]);
            }
        }
    }
    #pragma unroll
    for (int o = 1; o <= 2; o <<= 1)
        #pragma unroll
        for (int ridx = 0; ridx < 4; ridx++) {
            sum[ridx] += __shfl_xor_sync(FULLM, sum[ridx], o);
            sq[ridx]  += __shfl_xor_sync(FULLM, sq[ridx], o);
        }

    float2* sums = (float2*)sh;    // [128 local rows][2 wn] {sum, sq}
    if ((lane & 3) == 0) {
        #pragma unroll
        for (int ridx = 0; ridx < 4; ridx++) {
            int lr = wm * 32 + (lane >> 2) + (ridx >> 1) * 16 + (ridx & 1) * 8;
            sums[lr * 2 + wn] = make_float2(sum[ridx], sq[ridx]);
        }
    }
    __syncthreads();

    #pragma unroll
    for (int mi = 0; mi < 2; mi++) {
        #pragma unroll
        for (int h = 0; h < 2; h++) {
            int lr = wm * 32 + (lane >> 2) + mi * 16 + h * 8;
            float2 p0 = sums[lr * 2 + 0];
            float2 p1 = sums[lr * 2 + 1];
            float mu = (p0.x + p1.x) * (1.f / 128.f);
            float var = (p0.y + p1.y) * (1.f / 128.f) - mu * mu;
            float rstd = rsqrtf(var + 1e-5f);
            int r = row0 + lr;
            #pragma unroll
            for (int nj = 0; nj < 8; nj++) {
                int col = cbase + nj * 8;
                float v0 = (acc[mi][nj][h * 2 + 0] - mu) * rstd * lng[col] + lnb[col];
                float v1 = (acc[mi][nj][h * 2 + 1] - mu) * rstd * lng[col + 1] + lnb[col + 1];
                *(float2*)(outf + (size_t)r * 128 + col) = make_float2(v0, v1);
            }
        }
    }
}

// ---------------- exclusive scan of counts (4096), 1 block -----------------
__global__ void k_scan() {
    __shared__ int wsum[32];
    const int t = threadIdx.x;
    int v[4];
    #pragma unroll
    for (int i = 0; i < 4; i++) v[i] = g_counts[t * 4 + i];
    int sum = v[0] + v[1] + v[2] + v[3];
    const int lane = t & 31, w = t >> 5;
    int sc = sum;
    #pragma unroll
    for (int o = 1; o < 32; o <<= 1) {
        int n = __shfl_up_sync(FULLM, sc, o);
        if (lane >= o) sc += n;
    }
    if (lane == 31) wsum[w] = sc;
    __syncthreads();
    if (w == 0) {
        int ws = wsum[lane];
        #pragma unroll
        for (int o = 1; o < 32; o <<= 1) {
            int n = __shfl_up_sync(FULLM, ws, o);
            if (lane >= o) ws += n;
        }
        wsum[lane] = ws;
    }
    __syncthreads();
    int base = (w > 0 ? wsum[w - 1] : 0) + sc - sum;
    #pragma unroll
    for (int i = 0; i < 4; i++) { g_offsets[t * 4 + i] = base; base += v[i]; }
}

// ---------------- bucket scatter --------------------------------------------
__global__ void k_scatter(const int* __restrict__ idx) {
    int r = blockIdx.x * blockDim.x + threadIdx.x;
    if (r < BN) {
        int a = idx[r];
        int p = atomicAdd(&g_cursor[a], 1);
        g_bucket[g_offsets[a] + p] = r;
    }
}

// ---------------- paired warp reduction (for query norms) -------------------
__device__ __forceinline__ float pairred(float a0, float a1, int lane) {
    float x = (lane < 16) ? a1 : a0;
    x = __shfl_xor_sync(FULLM, x, 16);
    float t = ((lane < 16) ? a0 : a1) + x;
    t += __shfl_xor_sync(FULLM, t, 8);
    t += __shfl_xor_sync(FULLM, t, 4);
    t += __shfl_xor_sync(FULLM, t, 2);
    t += __shfl_xor_sync(FULLM, t, 1);
    return t;
}

// ---------------- fused attention (read+write) + intensity + histogram -----
__global__ void __launch_bounds__(256)
k_attn(const float* __restrict__ mem, const int* __restrict__ idx,
       const float* __restrict__ wq, const float* __restrict__ Wg,
       const float* __restrict__ bg)
{
    const int t = threadIdx.x, lane = t & 31;
    const int r = blockIdx.x * 8 + (t >> 5);
    const int a = idx[r];

    float4 qr = *(const float4*)(g_pqr + (size_t)r * 128 + lane * 4);
    float4 qw = *(const float4*)(g_pqw + (size_t)r * 128 + lane * 4);
    float nr0 = qr.x*qr.x + qr.y*qr.y + qr.z*qr.z + qr.w*qr.w;
    float nw0 = qw.x*qw.x + qw.y*qw.y + qw.z*qw.z + qw.w*qw.w;
    float nn = pairred(nr0, nw0, lane);        // lanes<16: |qr|^2, >=16: |qw|^2
    float inv = 1.f / fmaxf(sqrtf(nn), EPSN);

    // intensity: sigmoid(wq . Wg + bg) + agent histogram
    {
        float4 x = *(const float4*)(wq + (size_t)r * 128 + lane * 4);
        float4 g = *(const float4*)(Wg + lane * 4);
        float p = x.x * g.x + x.y * g.y + x.z * g.z + x.w * g.w;
        #pragma unroll
        for (int o = 16; o > 0; o >>= 1) p += __shfl_xor_sync(FULLM, p, o);
        if (lane == 0) {
            g_inten[r] = 1.f / (1.f + __expf(-(p + bg[0])));
            atomicAdd(&g_counts[a], 1);
        }
    }

    float rmn = g_rmn[a * 16 + (lane & 15)];   // reciprocal slot norms (pre-scaled)

    float ax = 0.f, ay = 0.f, az = 0.f, aw2 = 0.f, lr = 0.f, lw = 0.f, myw = 0.f;
    const float* mrow = mem + (size_t)a * 2048;
    #pragma unroll
    for (int j = 0; j < 8; j++) {
        const int s0 = 2 * j, s1 = 2 * j + 1;
        float4 m0 = *(const float4*)(mrow + s0 * 128 + lane * 4);
        float4 m1 = *(const float4*)(mrow + s1 * 128 + lane * 4);
        float p0 = m0.x*qr.x + m0.y*qr.y + m0.z*qr.z + m0.w*qr.w;   // m0.qr
        float p1 = m0.x*qw.x + m0.y*qw.y + m0.z*qw.z + m0.w*qw.w;   // m0.qw
        float p2 = m1.x*qr.x + m1.y*qr.y + m1.z*qr.z + m1.w*qr.w;   // m1.qr
        float p3 = m1.x*qw.x + m1.y*qw.y + m1.z*qw.z + m1.w*qw.w;   // m1.qw

        float x1 = (lane & 16) ? p0 : p1;
        x1 = __shfl_xor_sync(FULLM, x1, 16);
        float A = ((lane & 16) ? p1 : p0) + x1;    // <16: p0, >=16: p1
        float x2 = (lane & 16) ? p2 : p3;
        x2 = __shfl_xor_sync(FULLM, x2, 16);
        float Bv = ((lane & 16) ? p3 : p2) + x2;   // <16: p2, >=16: p3
        float x3 = (lane & 8) ? A : Bv;
        x3 = __shfl_xor_sync(FULLM, x3, 8);
        float C = ((lane & 8) ? Bv : A) + x3;      // octets: p0|p2|p1|p3
        C += __shfl_xor_sync(FULLM, C, 4);
        C += __shfl_xor_sync(FULLM, C, 2);
        C += __shfl_xor_sync(FULLM, C, 1);

        float rmnj = __shfl_sync(FULLM, rmn, s0 + ((lane >> 3) & 1));
        float e = __expf(C * inv * rmnj);          // one exp per thread
        float er0 = __shfl_sync(FULLM, e, 0);
        float er1 = __shfl_sync(FULLM, e, 8);
        float ew0 = __shfl_sync(FULLM, e, 16);
        float ew1 = __shfl_sync(FULLM, e, 24);
        lr += er0 + er1;
        lw += ew0 + ew1;
        ax  = fmaf(er0, m0.x, fmaf(er1, m1.x, ax));
        ay  = fmaf(er0, m0.y, fmaf(er1, m1.y, ay));
        az  = fmaf(er0, m0.z, fmaf(er1, m1.z, az));
        aw2 = fmaf(er0, m0.w, fmaf(er1, m1.w, aw2));
        if (lane == s0) myw = ew0;
        if (lane == s1) myw = ew1;
    }
    float invl = 1.f / lr;
    *(float4*)(g_read + (size_t)r * 128 + lane * 4) =
        make_float4(ax * invl, ay * invl, az * invl, aw2 * invl);
    if (lane < 16) g_ww[r * 16 + lane] = myw / lw;
}

// ---------------- per-agent gather-reduce + memory update + l2norm ---------
__global__ void k_agent(const float* __restrict__ mem, float* __restrict__ outm)
{
    __shared__ float part[8][8];
    __shared__ float nsh[16];
    const int a = blockIdx.x;
    const int t = threadIdx.x;
    const int d = t & 127;
    const int sg = t >> 7;
    const float* mrow = mem + (size_t)a * 2048;
    float* orow = outm + (size_t)a * 2048;
    const int cnt = g_counts[a];
    if (cnt == 0) {
        #pragma unroll
        for (int k = 0; k < 8; k++)
            orow[(sg * 8 + k) * 128 + d] = mrow[(sg * 8 + k) * 128 + d];
        return;
    }
    const int base = g_offsets[a];
    float E[8], A[8];
    #pragma unroll
    for (int k = 0; k < 8; k++) { E[k] = 0.f; A[k] = 0.f; }

    for (int i = 0; i < cnt; i++) {
        int r = g_bucket[base + i];
        float eld = g_el[(size_t)r * 128 + d];
        float ald = g_al[(size_t)r * 128 + d];
        float itn = g_inten[r];
        float4 w0 = *(const float4*)(g_ww + r * 16 + sg * 8);      // uniform addr
        float4 w1 = *(const float4*)(g_ww + r * 16 + sg * 8 + 4);  // (L1 broadcast)
        float ei = itn / (1.f + __expf(-eld));                    // erase * intensity
        float ai = itn * (1.f - 2.f / (__expf(2.f * ald) + 1.f)); // add * intensity
        E[0] = fmaf(w0.x, ei, E[0]); A[0] = fmaf(w0.x, ai, A[0]);
        E[1] = fmaf(w0.y, ei, E[1]); A[1] = fmaf(w0.y, ai, A[1]);
        E[2] = fmaf(w0.z, ei, E[2]); A[2] = fmaf(w0.z, ai, A[2]);
        E[3] = fmaf(w0.w, ei, E[3]); A[3] = fmaf(w0.w, ai, A[3]);
        E[4] = fmaf(w1.x, ei, E[4]); A[4] = fmaf(w1.x, ai, A[4]);
        E[5] = fmaf(w1.y, ei, E[5]); A[5] = fmaf(w1.y, ai, A[5]);
        E[6] = fmaf(w1.z, ei, E[6]); A[6] = fmaf(w1.z, ai, A[6]);
        E[7] = fmaf(w1.w, ei, E[7]); A[7] = fmaf(w1.w, ai, A[7]);
    }

    float nv[8], p2[8];
    #pragma unroll
    for (int k = 0; k < 8; k++) {
        float m = mrow[(sg * 8 + k) * 128 + d];
        nv[k] = m * (1.f - E[k]) + A[k];
        p2[k] = nv[k] * nv[k];
    }
    #pragma unroll
    for (int o = 16; o > 0; o >>= 1) {
        #pragma unroll
        for (int k = 0; k < 8; k++) p2[k] += __shfl_xor_sync(FULLM, p2[k], o);
    }
    const int wp = t >> 5, lane = t & 31;
    if (lane == 0) {
        #pragma unroll
        for (int k = 0; k < 8; k++) part[wp][k] = p2[k];
    }
    __syncthreads();
    if (t < 16) {
        float n2 = part[(t >> 3) * 4 + 0][t & 7] + part[(t >> 3) * 4 + 1][t & 7]
                 + part[(t >> 3) * 4 + 2][t & 7] + part[(t >> 3) * 4 + 3][t & 7];
        nsh[t] = fmaxf(sqrtf(n2), EPSN);
    }
    __syncthreads();
    #pragma unroll
    for (int k = 0; k < 8; k++)
        orow[(sg * 8 + k) * 128 + d] = nv[k] / nsh[sg * 8 + k];
}

// ---------------- launch: fork-join graph ------------------------------------
//   main: mnorm -> gemmA(pqr,pqw) -> attn -> scan -> scatter -> [wait gemmB] agent -> [wait fuse]
//   s2:   [after gemmA] gemmB(el,al)          (overlaps attn + fuse)
//   s3:   [after attn]  fuse                  (overlaps scan/scatter/agent)
extern "C" void kernel_launch(void* const* d_in, const int* in_sizes, int n_in,
                              void* d_out, int out_size)
{
    const float* queries  = (const float*)d_in[0];
    const float* wqueries = (const float*)d_in[1];
    const float* memory   = (const float*)d_in[2];
    const float* Wq  = (const float*)d_in[3];
    const float* bq  = (const float*)d_in[4];
    const float* We  = (const float*)d_in[5];
    const float* be  = (const float*)d_in[6];
    const float* Wa  = (const float*)d_in[7];
    const float* ba  = (const float*)d_in[8];
    const float* Wf  = (const float*)d_in[9];
    const float* bf  = (const float*)d_in[10];
    const float* lng = (const float*)d_in[11];
    const float* lnb = (const float*)d_in[12];
    const float* Wg  = (const float*)d_in[13];
    const float* bg  = (const float*)d_in[14];
    const int*   idx = (const int*)d_in[15];

    float* outf = (float*)d_out;                 // fused_read [B,128]
    float* outm = outf + (size_t)BN * DD;        // new_memory [4096,16,128]

    const int gemm_smem = 2 * 128 * LDK * 4;     // 69632

    // streams/events created once on the first (uncaptured correctness) call;
    // reused verbatim on the capture call. Work issued is identical per call.
    static cudaStream_t s2 = nullptr, s3 = nullptr;
    static cudaEvent_t e1, e2, e3, e4;
    if (s2 == nullptr) {
        cudaStreamCreateWithFlags(&s2, cudaStreamNonBlocking);
        cudaStreamCreateWithFlags(&s3, cudaStreamNonBlocking);
        cudaEventCreateWithFlags(&e1, cudaEventDisableTiming);
        cudaEventCreateWithFlags(&e2, cudaEventDisableTiming);
        cudaEventCreateWithFlags(&e3, cudaEventDisableTiming);
        cudaEventCreateWithFlags(&e4, cudaEventDisableTiming);
        cudaFuncSetAttribute(k_gemm_tc, cudaFuncAttributeMaxDynamicSharedMemorySize, gemm_smem);
        cudaFuncSetAttribute(k_fuse,    cudaFuncAttributeMaxDynamicSharedMemorySize, gemm_smem);
    }

    k_mnorm<<<NA * NS / 8, 256>>>(memory);                         // + zero counts
    k_gemm_tc<<<dim3(BN / 128, 2), 256, gemm_smem>>>(
        queries, wqueries, Wq, bq, We, be, Wa, ba, 0);             // pqr, pqw
    cudaEventRecord(e1, (cudaStream_t)0);

    cudaStreamWaitEvent(s2, e1, 0);
    k_gemm_tc<<<dim3(BN / 128, 2), 256, gemm_smem, s2>>>(
        queries, wqueries, Wq, bq, We, be, Wa, ba, 2);             // el, al
    cudaEventRecord(e2, s2);

    k_attn<<<BN / 8, 256>>>(memory, idx, wqueries, Wg, bg);
    cudaEventRecord(e3, (cudaStream_t)0);

    cudaStreamWaitEvent(s3, e3, 0);
    k_fuse<<<BN / 128, 256, gemm_smem, s3>>>(Wf, bf, lng, lnb, outf);
    cudaEventRecord(e4, s3);

    k_scan<<<1, 1024>>>();
    k_scatter<<<BN / 256, 256>>>(idx);
    cudaStreamWaitEvent((cudaStream_t)0, e2, 0);                   // join gemmB
    k_agent<<<NA, 256>>>(memory, outm);
    cudaStreamWaitEvent((cudaStream_t)0, e4, 0);                   // join fuse
}